// round 2
// baseline (speedup 1.0000x reference)
#include <cuda_runtime.h>
#include <math.h>

#define NN 200000
#define FF 128
#define EE 600000
#define K1 384   // 3F
#define H1 256   // 2F

// Scratch (static __device__ arrays: allocation-free, graph-safe)
__device__ int   g_min1[NN];
__device__ int   g_min2[NN];
__device__ float g_h[(size_t)NN * H1];     // relu(ctx@w1+b1)  [N,256]
__device__ float g_proc[(size_t)NN * FF];  // LN(h@w2+b2), only for updated nodes

// ---------------------------------------------------------------------------
// Graph: two smallest distinct neighbors
// ---------------------------------------------------------------------------
__global__ void k_init() {
    int i = blockIdx.x * blockDim.x + threadIdx.x;
    if (i < NN) { g_min1[i] = NN; g_min2[i] = NN; }
}

__global__ void k_pass1(const int* __restrict__ ei) {
    int e = blockIdx.x * blockDim.x + threadIdx.x;
    if (e >= EE) return;
    int s = ei[e], d = ei[EE + e];
    if (s != d) { atomicMin(&g_min1[s], d); atomicMin(&g_min1[d], s); }
}

__global__ void k_pass2(const int* __restrict__ ei) {
    int e = blockIdx.x * blockDim.x + threadIdx.x;
    if (e >= EE) return;
    int s = ei[e], d = ei[EE + e];
    if (s != d) {
        if (d != g_min1[s]) atomicMin(&g_min2[s], d);
        if (s != g_min1[d]) atomicMin(&g_min2[d], s);
    }
}

// ---------------------------------------------------------------------------
// GEMM1: h = relu([x | x[n0] | x[n1]] @ w1 + b1)   A gathered on the fly.
// Tile 128x128, K-step 16, 256 threads, 8x8 microtile.
// grid = (2, ceil(N/128))
// ---------------------------------------------------------------------------
__global__ void __launch_bounds__(256) k_gemm1(const float* __restrict__ x,
                                               const float* __restrict__ w1,
                                               const float* __restrict__ b1) {
    __shared__ float As[16][128];
    __shared__ float Bs[16][128];
    __shared__ int   sN[2][128];

    const int t  = threadIdx.x;
    const int bx = blockIdx.x;          // 0..1 (column tile of 256)
    const int r0 = blockIdx.y * 128;

    if (t < 128) {
        int r = min(r0 + t, NN - 1);
        sN[0][t] = min(g_min1[r], NN - 1);
        sN[1][t] = min(g_min2[r], NN - 1);
    }
    __syncthreads();

    const int tx = t & 15, ty = t >> 4;
    const int ai   = t >> 1;            // A tile row this thread loads
    const int aseg = (t & 1) * 2;       // float4 segment base (k/4)
    const int bk   = t >> 4;            // B tile k-row
    const int bj   = (t & 15) * 8;      // B tile col base
    const int selfr = min(r0 + ai, NN - 1);

    float acc[8][8];
#pragma unroll
    for (int i = 0; i < 8; i++)
#pragma unroll
        for (int j = 0; j < 8; j++) acc[i][j] = 0.f;

    for (int kk = 0; kk < K1; kk += 16) {
        const int sel  = kk >> 7;       // which of {self, n0, n1}; constant per k-tile
        const int koff = kk & 127;
        const int arow = (sel == 0) ? selfr : sN[sel - 1][ai];
        const float4* ap = (const float4*)(x + (size_t)arow * FF + koff);
        float4 a0 = ap[aseg];
        float4 a1 = ap[aseg + 1];
        const float4* bp = (const float4*)(w1 + (size_t)(kk + bk) * H1 + bx * 128 + bj);
        float4 bv0 = bp[0];
        float4 bv1 = bp[1];

        __syncthreads();
        {
            int kb = aseg * 4;
            As[kb + 0][ai] = a0.x; As[kb + 1][ai] = a0.y;
            As[kb + 2][ai] = a0.z; As[kb + 3][ai] = a0.w;
            As[kb + 4][ai] = a1.x; As[kb + 5][ai] = a1.y;
            As[kb + 6][ai] = a1.z; As[kb + 7][ai] = a1.w;
            *(float4*)&Bs[bk][bj]     = bv0;
            *(float4*)&Bs[bk][bj + 4] = bv1;
        }
        __syncthreads();

#pragma unroll
        for (int k = 0; k < 16; k++) {
            float4 ra0 = *(const float4*)&As[k][ty * 8];
            float4 ra1 = *(const float4*)&As[k][ty * 8 + 4];
            float4 rb0 = *(const float4*)&Bs[k][tx * 8];
            float4 rb1 = *(const float4*)&Bs[k][tx * 8 + 4];
            float ar[8] = {ra0.x, ra0.y, ra0.z, ra0.w, ra1.x, ra1.y, ra1.z, ra1.w};
            float br[8] = {rb0.x, rb0.y, rb0.z, rb0.w, rb1.x, rb1.y, rb1.z, rb1.w};
#pragma unroll
            for (int i = 0; i < 8; i++)
#pragma unroll
                for (int j = 0; j < 8; j++) acc[i][j] = fmaf(ar[i], br[j], acc[i][j]);
        }
    }

    // epilogue: bias + relu -> g_h
    float breg[8];
#pragma unroll
    for (int j = 0; j < 8; j++) breg[j] = b1[bx * 128 + tx * 8 + j];
#pragma unroll
    for (int i = 0; i < 8; i++) {
        int r = r0 + ty * 8 + i;
        if (r < NN) {
            float v[8];
#pragma unroll
            for (int j = 0; j < 8; j++) v[j] = fmaxf(acc[i][j] + breg[j], 0.f);
            float4* hp = (float4*)(g_h + (size_t)r * H1 + bx * 128 + tx * 8);
            hp[0] = make_float4(v[0], v[1], v[2], v[3]);
            hp[1] = make_float4(v[4], v[5], v[6], v[7]);
        }
    }
}

// ---------------------------------------------------------------------------
// GEMM2 + LayerNorm + output select:
//   proc = LN(h @ w2 + b2); out_updated = upd ? proc : x; stash proc for murray
// Tile 128 rows x 128 cols (full width), K=256.
// grid = ceil(N/128)
// ---------------------------------------------------------------------------
__global__ void __launch_bounds__(256) k_gemm2(const float* __restrict__ x,
                                               const float* __restrict__ w2,
                                               const float* __restrict__ b2,
                                               const float* __restrict__ lng,
                                               const float* __restrict__ lnb,
                                               const int*   __restrict__ types,
                                               float* __restrict__ out) {
    __shared__ float As[16][128];
    __shared__ float Bs[16][128];

    const int t  = threadIdx.x;
    const int r0 = blockIdx.x * 128;
    const int tx = t & 15, ty = t >> 4;
    const int ai   = t >> 1;
    const int aseg = (t & 1) * 2;
    const int bk   = t >> 4;
    const int bj   = (t & 15) * 8;
    const int arow = min(r0 + ai, NN - 1);

    float acc[8][8];
#pragma unroll
    for (int i = 0; i < 8; i++)
#pragma unroll
        for (int j = 0; j < 8; j++) acc[i][j] = 0.f;

    for (int kk = 0; kk < H1; kk += 16) {
        const float4* ap = (const float4*)(g_h + (size_t)arow * H1 + kk);
        float4 a0 = ap[aseg];
        float4 a1 = ap[aseg + 1];
        const float4* bp = (const float4*)(w2 + (size_t)(kk + bk) * FF + bj);
        float4 bv0 = bp[0];
        float4 bv1 = bp[1];

        __syncthreads();
        {
            int kb = aseg * 4;
            As[kb + 0][ai] = a0.x; As[kb + 1][ai] = a0.y;
            As[kb + 2][ai] = a0.z; As[kb + 3][ai] = a0.w;
            As[kb + 4][ai] = a1.x; As[kb + 5][ai] = a1.y;
            As[kb + 6][ai] = a1.z; As[kb + 7][ai] = a1.w;
            *(float4*)&Bs[bk][bj]     = bv0;
            *(float4*)&Bs[bk][bj + 4] = bv1;
        }
        __syncthreads();

#pragma unroll
        for (int k = 0; k < 16; k++) {
            float4 ra0 = *(const float4*)&As[k][ty * 8];
            float4 ra1 = *(const float4*)&As[k][ty * 8 + 4];
            float4 rb0 = *(const float4*)&Bs[k][tx * 8];
            float4 rb1 = *(const float4*)&Bs[k][tx * 8 + 4];
            float ar[8] = {ra0.x, ra0.y, ra0.z, ra0.w, ra1.x, ra1.y, ra1.z, ra1.w};
            float br[8] = {rb0.x, rb0.y, rb0.z, rb0.w, rb1.x, rb1.y, rb1.z, rb1.w};
#pragma unroll
            for (int i = 0; i < 8; i++)
#pragma unroll
                for (int j = 0; j < 8; j++) acc[i][j] = fmaf(ar[i], br[j], acc[i][j]);
        }
    }

    // bias + LayerNorm (row spans 16 lanes in tx direction; shuffle-reduce)
    float breg[8], greg[8], bereg[8];
#pragma unroll
    for (int j = 0; j < 8; j++) {
        int c = tx * 8 + j;
        breg[j] = b2[c]; greg[j] = lng[c]; bereg[j] = lnb[c];
    }
#pragma unroll
    for (int i = 0; i < 8; i++) {
        float s = 0.f, q = 0.f;
#pragma unroll
        for (int j = 0; j < 8; j++) {
            float v = acc[i][j] + breg[j];
            acc[i][j] = v;
            s += v; q += v * v;
        }
#pragma unroll
        for (int m = 1; m < 16; m <<= 1) {
            s += __shfl_xor_sync(0xffffffffu, s, m);
            q += __shfl_xor_sync(0xffffffffu, q, m);
        }
        float mean = s * (1.f / FF);
        float var  = q * (1.f / FF) - mean * mean;
        float rstd = rsqrtf(var + 1e-5f);
#pragma unroll
        for (int j = 0; j < 8; j++)
            acc[i][j] = (acc[i][j] - mean) * rstd * greg[j] + bereg[j];
    }

    // write updated output (+ stash proc for murray where needed)
#pragma unroll
    for (int i = 0; i < 8; i++) {
        int r = r0 + ty * 8 + i;
        if (r < NN) {
            bool upd = (types[r] == 1) && (g_min1[r] < NN) && (g_min2[r] < NN);
            float4* op = (float4*)(out + (size_t)r * FF + tx * 8);
            if (upd) {
                float4 p0 = make_float4(acc[i][0], acc[i][1], acc[i][2], acc[i][3]);
                float4 p1 = make_float4(acc[i][4], acc[i][5], acc[i][6], acc[i][7]);
                op[0] = p0; op[1] = p1;
                float4* pp = (float4*)(g_proc + (size_t)r * FF + tx * 8);
                pp[0] = p0; pp[1] = p1;
            } else {
                const float4* xp = (const float4*)(x + (size_t)r * FF + tx * 8);
                op[0] = xp[0]; op[1] = xp[1];
            }
        }
    }
}

// ---------------------------------------------------------------------------
// Murray head: sigmoid(relu(proc@mw1+mb1)@mw2+mb2), one warp per node,
// skipping nodes that don't need the compute (warp-uniform predicate).
// ---------------------------------------------------------------------------
__global__ void __launch_bounds__(256) k_murray(const int*   __restrict__ types,
                                                const float* __restrict__ mw1,
                                                const float* __restrict__ mb1,
                                                const float* __restrict__ mw2,
                                                const float* __restrict__ mb2,
                                                float* __restrict__ out) {
    __shared__ float w1s[128 * 64];
    __shared__ float b1s[64];
    __shared__ float w2s[64];

    const int t = threadIdx.x;
    for (int i = t; i < 128 * 64; i += 256) w1s[i] = mw1[i];
    if (t < 64) { b1s[t] = mb1[t]; w2s[t] = mw2[t]; }
    __syncthreads();

    const float bias2 = mb2[0];
    const int lane = t & 31;
    const int gw   = (blockIdx.x * 256 + t) >> 5;
    const int nw   = gridDim.x * 8;
    float* mo = out + (size_t)NN * FF;

    for (int r = gw; r < NN; r += nw) {
        bool isbif = (types[r] == 1);
        if (!isbif) { if (lane == 0) mo[r] = 0.f; continue; }
        bool has2 = (g_min1[r] < NN) && (g_min2[r] < NN);
        if (!has2) { if (lane == 0) mo[r] = 0.5f; continue; }

        float4 pr = ((const float4*)(g_proc + (size_t)r * FF))[lane];  // k = lane*4..+3
        float m0 = b1s[2 * lane], m1 = b1s[2 * lane + 1];
#pragma unroll
        for (int k4 = 0; k4 < 32; k4++) {
            float vx = __shfl_sync(0xffffffffu, pr.x, k4);
            float vy = __shfl_sync(0xffffffffu, pr.y, k4);
            float vz = __shfl_sync(0xffffffffu, pr.z, k4);
            float vw = __shfl_sync(0xffffffffu, pr.w, k4);
            float2 w0 = ((const float2*)&w1s[(k4 * 4 + 0) * 64])[lane];
            float2 w1v = ((const float2*)&w1s[(k4 * 4 + 1) * 64])[lane];
            float2 w2v = ((const float2*)&w1s[(k4 * 4 + 2) * 64])[lane];
            float2 w3v = ((const float2*)&w1s[(k4 * 4 + 3) * 64])[lane];
            m0 = fmaf(vx, w0.x, fmaf(vy, w1v.x, fmaf(vz, w2v.x, fmaf(vw, w3v.x, m0))));
            m1 = fmaf(vx, w0.y, fmaf(vy, w1v.y, fmaf(vz, w2v.y, fmaf(vw, w3v.y, m1))));
        }
        float p = fmaxf(m0, 0.f) * w2s[2 * lane] + fmaxf(m1, 0.f) * w2s[2 * lane + 1];
#pragma unroll
        for (int m = 16; m; m >>= 1) p += __shfl_xor_sync(0xffffffffu, p, m);
        if (lane == 0) mo[r] = 1.f / (1.f + expf(-(p + bias2)));
    }
}

// ---------------------------------------------------------------------------
extern "C" void kernel_launch(void* const* d_in, const int* in_sizes, int n_in,
                              void* d_out, int out_size) {
    const float* x   = (const float*)d_in[0];
    const int*   ei  = (const int*)d_in[1];
    const int*   ty  = (const int*)d_in[2];
    const float* w1  = (const float*)d_in[3];
    const float* b1  = (const float*)d_in[4];
    const float* w2  = (const float*)d_in[5];
    const float* b2  = (const float*)d_in[6];
    const float* lng = (const float*)d_in[7];
    const float* lnb = (const float*)d_in[8];
    const float* mw1 = (const float*)d_in[9];
    const float* mb1 = (const float*)d_in[10];
    const float* mw2 = (const float*)d_in[11];
    const float* mb2 = (const float*)d_in[12];
    float* out = (float*)d_out;

    k_init<<<(NN + 255) / 256, 256>>>();
    k_pass1<<<(EE + 255) / 256, 256>>>(ei);
    k_pass2<<<(EE + 255) / 256, 256>>>(ei);

    dim3 g1(2, (NN + 127) / 128);
    k_gemm1<<<g1, 256>>>(x, w1, b1);
    k_gemm2<<<(NN + 127) / 128, 256>>>(x, w2, b2, lng, lnb, ty, out);
    k_murray<<<592, 256>>>(ty, mw1, mb1, mw2, mb2, out);
}

// round 5
// speedup vs baseline: 1.8653x; 1.8653x over previous
#include <cuda_runtime.h>
#include <math.h>
#include <stdint.h>

#define NN 200000
#define FF 128
#define EE 600000
#define KP 20   // padded smem k-stride (conflict-free for mma fragment loads)

// ---------------- scratch ----------------
__device__ int   g_min1[NN];
__device__ int   g_min2[NN];
__device__ float g_w1t[256 * 384];        // w1t[n][k] = w1[k][n]
__device__ float g_w2t[128 * 256];        // w2t[n][k] = w2[k][n]
__device__ float g_h[(size_t)NN * 256];   // relu(ctx@w1+b1)
__device__ float g_proc[(size_t)NN * 128];

// ---------------- helpers ----------------
__device__ __forceinline__ uint32_t tf32r(float f) {
    uint32_t u;
    asm("cvt.rna.tf32.f32 %0, %1;" : "=r"(u) : "f"(f));
    return u;
}
__device__ __forceinline__ void mma8(float* c, const uint32_t* a, const uint32_t* b) {
    asm volatile(
        "mma.sync.aligned.m16n8k8.row.col.f32.tf32.tf32.f32 "
        "{%0,%1,%2,%3}, {%4,%5,%6,%7}, {%8,%9}, {%0,%1,%2,%3};"
        : "+f"(c[0]), "+f"(c[1]), "+f"(c[2]), "+f"(c[3])
        : "r"(a[0]), "r"(a[1]), "r"(a[2]), "r"(a[3]), "r"(b[0]), "r"(b[1]));
}

// ---------------- graph kernels ----------------
__global__ void k_init() {
    int i = blockIdx.x * blockDim.x + threadIdx.x;
    if (i < NN) { g_min1[i] = NN; g_min2[i] = NN; }
}
__global__ void k_pass1(const int* __restrict__ ei) {
    int e = blockIdx.x * blockDim.x + threadIdx.x;
    if (e >= EE) return;
    int s = ei[e], d = ei[EE + e];
    if (s != d) { atomicMin(&g_min1[s], d); atomicMin(&g_min1[d], s); }
}
__global__ void k_pass2(const int* __restrict__ ei) {
    int e = blockIdx.x * blockDim.x + threadIdx.x;
    if (e >= EE) return;
    int s = ei[e], d = ei[EE + e];
    if (s != d) {
        if (d != g_min1[s]) atomicMin(&g_min2[s], d);
        if (s != g_min1[d]) atomicMin(&g_min2[d], s);
    }
}
__global__ void k_prep(const float* __restrict__ w1, const float* __restrict__ w2) {
    int i = blockIdx.x * blockDim.x + threadIdx.x;
    if (i < 256 * 384) { int n = i / 384, k = i % 384; g_w1t[i] = w1[k * 256 + n]; }
    if (i < 128 * 256) { int n = i / 256, k = i % 256; g_w2t[i] = w2[k * 128 + n]; }
}

// ---------------------------------------------------------------------------
// GEMM1 (tf32 mma): g_h = relu([x | x[n0] | x[n1]] @ w1 + b1)
// block 128(m) x 128(n), K=384 in 24 chunks of 16; grid (2, ceil(N/128))
// warps: 4(m) x 2(n); warp tile 32x64; m16n8k8
// ---------------------------------------------------------------------------
__global__ void __launch_bounds__(256, 2) k_gemm1(const float* __restrict__ x,
                                                  const float* __restrict__ b1) {
    __shared__ uint32_t As[2][128 * KP];
    __shared__ uint32_t Bs[2][128 * KP];
    __shared__ int sN[2][128];

    const int t = threadIdx.x, lane = t & 31, w = t >> 5;
    const int bx = blockIdx.x, r0 = blockIdx.y * 128;

    if (t < 128) {
        int r = min(r0 + t, NN - 1);
        sN[0][t] = min(g_min1[r], NN - 1);
        sN[1][t] = min(g_min2[r], NN - 1);
    }
    __syncthreads();

    const int row = t >> 1, kh = (t & 1) * 8;
    const int selfr = min(r0 + row, NN - 1);
    const int mw = w & 3, nw = w >> 2;
    const int gid = lane >> 2, tig = lane & 3;

    float acc[2][8][4];
#pragma unroll
    for (int ms = 0; ms < 2; ms++)
#pragma unroll
        for (int nt = 0; nt < 8; nt++)
#pragma unroll
            for (int j = 0; j < 4; j++) acc[ms][nt][j] = 0.f;

    float4 av0, av1, bv0, bv1;
    {   // prologue: chunk 0 (sel = self)
        const float4* ap = (const float4*)(x + (size_t)selfr * 128 + kh);
        av0 = ap[0]; av1 = ap[1];
        const float4* bp = (const float4*)(g_w1t + (size_t)(bx * 128 + row) * 384 + kh);
        bv0 = bp[0]; bv1 = bp[1];
    }

    const int si = row * KP + kh;
    for (int c = 0; c < 24; c++) {
        const int b = c & 1;
        uint32_t* A = As[b];
        uint32_t* B = Bs[b];
        {
            uint32_t ta[8] = { tf32r(av0.x), tf32r(av0.y), tf32r(av0.z), tf32r(av0.w),
                               tf32r(av1.x), tf32r(av1.y), tf32r(av1.z), tf32r(av1.w) };
            uint32_t tbv[8] = { tf32r(bv0.x), tf32r(bv0.y), tf32r(bv0.z), tf32r(bv0.w),
                                tf32r(bv1.x), tf32r(bv1.y), tf32r(bv1.z), tf32r(bv1.w) };
            *(float4*)&A[si]     = *(float4*)&ta[0];
            *(float4*)&A[si + 4] = *(float4*)&ta[4];
            *(float4*)&B[si]     = *(float4*)&tbv[0];
            *(float4*)&B[si + 4] = *(float4*)&tbv[4];
        }
        __syncthreads();
        if (c + 1 < 24) {
            int cn = c + 1;
            int sel = cn >> 3, koff = (cn & 7) * 16 + kh;
            int src = (sel == 0) ? selfr : sN[sel - 1][row];
            const float4* ap = (const float4*)(x + (size_t)src * 128 + koff);
            av0 = ap[0]; av1 = ap[1];
            const float4* bp = (const float4*)(g_w1t + (size_t)(bx * 128 + row) * 384 + cn * 16 + kh);
            bv0 = bp[0]; bv1 = bp[1];
        }
#pragma unroll
        for (int k8 = 0; k8 < 2; k8++) {
            const int kb = k8 * 8;
            uint32_t af[2][4];
#pragma unroll
            for (int ms = 0; ms < 2; ms++) {
                int m = mw * 32 + ms * 16;
                af[ms][0] = A[(m + gid) * KP + kb + tig];
                af[ms][1] = A[(m + 8 + gid) * KP + kb + tig];
                af[ms][2] = A[(m + gid) * KP + kb + tig + 4];
                af[ms][3] = A[(m + 8 + gid) * KP + kb + tig + 4];
            }
#pragma unroll
            for (int nt = 0; nt < 8; nt++) {
                int n = nw * 64 + nt * 8 + gid;
                uint32_t bf[2] = { B[n * KP + kb + tig], B[n * KP + kb + tig + 4] };
                mma8(acc[0][nt], af[0], bf);
                mma8(acc[1][nt], af[1], bf);
            }
        }
        __syncthreads();
    }

    // epilogue: bias + relu -> g_h (32B sectors fully covered per quad)
#pragma unroll
    for (int ms = 0; ms < 2; ms++) {
        int rl = r0 + mw * 32 + ms * 16 + gid;
#pragma unroll
        for (int nt = 0; nt < 8; nt++) {
            int col = bx * 128 + nw * 64 + nt * 8 + tig * 2;
            float bb0 = __ldg(&b1[col]), bb1 = __ldg(&b1[col + 1]);
            if (rl < NN)
                *(float2*)&g_h[(size_t)rl * 256 + col] =
                    make_float2(fmaxf(acc[ms][nt][0] + bb0, 0.f),
                                fmaxf(acc[ms][nt][1] + bb1, 0.f));
            if (rl + 8 < NN)
                *(float2*)&g_h[(size_t)(rl + 8) * 256 + col] =
                    make_float2(fmaxf(acc[ms][nt][2] + bb0, 0.f),
                                fmaxf(acc[ms][nt][3] + bb1, 0.f));
        }
    }
}

// ---------------------------------------------------------------------------
// GEMM2 (tf32 mma) + bias + LayerNorm + output select
// block 128(m) x 128(n), K=256 in 16 chunks; grid ceil(N/128)
// dynamic smem: A/B double buffers aliased with 128x132 C staging
// ---------------------------------------------------------------------------
__global__ void __launch_bounds__(256, 2) k_gemm2(const float* __restrict__ x,
                                                  const float* __restrict__ b2,
                                                  const float* __restrict__ lng,
                                                  const float* __restrict__ lnb,
                                                  const int* __restrict__ types,
                                                  float* __restrict__ out) {
    extern __shared__ char dsm[];
    uint32_t* AsB = (uint32_t*)dsm;                 // [2][128*KP]
    uint32_t* BsB = AsB + 2 * 128 * KP;             // [2][128*KP]
    float* Cst = (float*)dsm;                       // [128*132], used after mainloop

    __shared__ int   sCls[128];
    __shared__ float sb2[128], slg[128], slb[128];

    const int t = threadIdx.x, lane = t & 31, w = t >> 5;
    const int r0 = blockIdx.x * 128;

    if (t < 128) {
        int r = min(r0 + t, NN - 1);
        int m1 = g_min1[r], m2 = g_min2[r];
        sCls[t] = (types[r] == 1) ? ((m1 < NN && m2 < NN) ? 2 : 1) : 0;
        sb2[t] = b2[t]; slg[t] = lng[t]; slb[t] = lnb[t];
    }
    __syncthreads();

    const int row = t >> 1, kh = (t & 1) * 8;
    const int arow = min(r0 + row, NN - 1);
    const int mw = w & 3, nw = w >> 2;
    const int gid = lane >> 2, tig = lane & 3;

    float acc[2][8][4];
#pragma unroll
    for (int ms = 0; ms < 2; ms++)
#pragma unroll
        for (int nt = 0; nt < 8; nt++)
#pragma unroll
            for (int j = 0; j < 4; j++) acc[ms][nt][j] = 0.f;

    float4 av0, av1, bv0, bv1;
    {
        const float4* ap = (const float4*)(g_h + (size_t)arow * 256 + kh);
        av0 = ap[0]; av1 = ap[1];
        const float4* bp = (const float4*)(g_w2t + (size_t)row * 256 + kh);
        bv0 = bp[0]; bv1 = bp[1];
    }

    const int si = row * KP + kh;
    for (int c = 0; c < 16; c++) {
        const int b = c & 1;
        uint32_t* A = AsB + b * 128 * KP;
        uint32_t* B = BsB + b * 128 * KP;
        {
            uint32_t ta[8] = { tf32r(av0.x), tf32r(av0.y), tf32r(av0.z), tf32r(av0.w),
                               tf32r(av1.x), tf32r(av1.y), tf32r(av1.z), tf32r(av1.w) };
            uint32_t tbv[8] = { tf32r(bv0.x), tf32r(bv0.y), tf32r(bv0.z), tf32r(bv0.w),
                                tf32r(bv1.x), tf32r(bv1.y), tf32r(bv1.z), tf32r(bv1.w) };
            *(float4*)&A[si]     = *(float4*)&ta[0];
            *(float4*)&A[si + 4] = *(float4*)&ta[4];
            *(float4*)&B[si]     = *(float4*)&tbv[0];
            *(float4*)&B[si + 4] = *(float4*)&tbv[4];
        }
        __syncthreads();
        if (c + 1 < 16) {
            int cn = c + 1;
            const float4* ap = (const float4*)(g_h + (size_t)arow * 256 + cn * 16 + kh);
            av0 = ap[0]; av1 = ap[1];
            const float4* bp = (const float4*)(g_w2t + (size_t)row * 256 + cn * 16 + kh);
            bv0 = bp[0]; bv1 = bp[1];
        }
#pragma unroll
        for (int k8 = 0; k8 < 2; k8++) {
            const int kb = k8 * 8;
            uint32_t af[2][4];
#pragma unroll
            for (int ms = 0; ms < 2; ms++) {
                int m = mw * 32 + ms * 16;
                af[ms][0] = A[(m + gid) * KP + kb + tig];
                af[ms][1] = A[(m + 8 + gid) * KP + kb + tig];
                af[ms][2] = A[(m + gid) * KP + kb + tig + 4];
                af[ms][3] = A[(m + 8 + gid) * KP + kb + tig + 4];
            }
#pragma unroll
            for (int nt = 0; nt < 8; nt++) {
                int n = nw * 64 + nt * 8 + gid;
                uint32_t bf[2] = { B[n * KP + kb + tig], B[n * KP + kb + tig + 4] };
                mma8(acc[0][nt], af[0], bf);
                mma8(acc[1][nt], af[1], bf);
            }
        }
        __syncthreads();
    }

    // stage bias-added C into smem (132-pad rows)
#pragma unroll
    for (int ms = 0; ms < 2; ms++) {
        int rl = mw * 32 + ms * 16 + gid;
#pragma unroll
        for (int nt = 0; nt < 8; nt++) {
            int col = nw * 64 + nt * 8 + tig * 2;
            Cst[rl * 132 + col]           = acc[ms][nt][0] + sb2[col];
            Cst[rl * 132 + col + 1]       = acc[ms][nt][1] + sb2[col + 1];
            Cst[(rl + 8) * 132 + col]     = acc[ms][nt][2] + sb2[col];
            Cst[(rl + 8) * 132 + col + 1] = acc[ms][nt][3] + sb2[col + 1];
        }
    }
    __syncthreads();

    // per-row LayerNorm (two-pass over smem)
    if (t < 128) {
        float* rp = Cst + t * 132;
        float s = 0.f, q = 0.f;
#pragma unroll
        for (int j = 0; j < 32; j++) {
            float4 v = ((const float4*)rp)[j];
            s += v.x + v.y + v.z + v.w;
            q += v.x * v.x + v.y * v.y + v.z * v.z + v.w * v.w;
        }
        float mean = s * (1.f / 128.f);
        float var  = q * (1.f / 128.f) - mean * mean;
        float rs   = rsqrtf(var + 1e-5f);
#pragma unroll
        for (int j = 0; j < 32; j++) {
            float4 v = ((const float4*)rp)[j];
            v.x = (v.x - mean) * rs * slg[4 * j]     + slb[4 * j];
            v.y = (v.y - mean) * rs * slg[4 * j + 1] + slb[4 * j + 1];
            v.z = (v.z - mean) * rs * slg[4 * j + 2] + slb[4 * j + 2];
            v.w = (v.w - mean) * rs * slg[4 * j + 3] + slb[4 * j + 3];
            ((float4*)rp)[j] = v;
        }
    }
    __syncthreads();

    // coalesced output: upd ? proc : x ; stash proc for murray
    {
        const float4* x4 = (const float4*)x;
        float4* o4 = (float4*)out;
        float4* p4 = (float4*)g_proc;
        for (int idx = t; idx < 128 * 32; idx += 256) {
            int rl = idx >> 5, c4 = idx & 31;
            int rg = r0 + rl;
            if (rg < NN) {
                int cls = sCls[rl];
                float4 v;
                if (cls == 2) {
                    v = ((const float4*)(Cst + rl * 132))[c4];
                    p4[(size_t)rg * 32 + c4] = v;
                } else {
                    v = x4[(size_t)rg * 32 + c4];
                }
                o4[(size_t)rg * 32 + c4] = v;
            }
        }
    }
}

// ---------------------------------------------------------------------------
// Murray head (unchanged from passing round-2 kernel)
// ---------------------------------------------------------------------------
__global__ void __launch_bounds__(256) k_murray(const int*   __restrict__ types,
                                                const float* __restrict__ mw1,
                                                const float* __restrict__ mb1,
                                                const float* __restrict__ mw2,
                                                const float* __restrict__ mb2,
                                                float* __restrict__ out) {
    __shared__ float w1s[128 * 64];
    __shared__ float b1s[64];
    __shared__ float w2s[64];

    const int t = threadIdx.x;
    for (int i = t; i < 128 * 64; i += 256) w1s[i] = mw1[i];
    if (t < 64) { b1s[t] = mb1[t]; w2s[t] = mw2[t]; }
    __syncthreads();

    const float bias2 = mb2[0];
    const int lane = t & 31;
    const int gw   = (blockIdx.x * 256 + t) >> 5;
    const int nw   = gridDim.x * 8;
    float* mo = out + (size_t)NN * FF;

    for (int r = gw; r < NN; r += nw) {
        bool isbif = (types[r] == 1);
        if (!isbif) { if (lane == 0) mo[r] = 0.f; continue; }
        bool has2 = (g_min1[r] < NN) && (g_min2[r] < NN);
        if (!has2) { if (lane == 0) mo[r] = 0.5f; continue; }

        float4 pr = ((const float4*)(g_proc + (size_t)r * FF))[lane];
        float m0 = b1s[2 * lane], m1 = b1s[2 * lane + 1];
#pragma unroll
        for (int k4 = 0; k4 < 32; k4++) {
            float vx = __shfl_sync(0xffffffffu, pr.x, k4);
            float vy = __shfl_sync(0xffffffffu, pr.y, k4);
            float vz = __shfl_sync(0xffffffffu, pr.z, k4);
            float vw = __shfl_sync(0xffffffffu, pr.w, k4);
            float2 w0  = ((const float2*)&w1s[(k4 * 4 + 0) * 64])[lane];
            float2 w1v = ((const float2*)&w1s[(k4 * 4 + 1) * 64])[lane];
            float2 w2v = ((const float2*)&w1s[(k4 * 4 + 2) * 64])[lane];
            float2 w3v = ((const float2*)&w1s[(k4 * 4 + 3) * 64])[lane];
            m0 = fmaf(vx, w0.x, fmaf(vy, w1v.x, fmaf(vz, w2v.x, fmaf(vw, w3v.x, m0))));
            m1 = fmaf(vx, w0.y, fmaf(vy, w1v.y, fmaf(vz, w2v.y, fmaf(vw, w3v.y, m1))));
        }
        float p = fmaxf(m0, 0.f) * w2s[2 * lane] + fmaxf(m1, 0.f) * w2s[2 * lane + 1];
#pragma unroll
        for (int m = 16; m; m >>= 1) p += __shfl_xor_sync(0xffffffffu, p, m);
        if (lane == 0) mo[r] = 1.f / (1.f + expf(-(p + bias2)));
    }
}

// ---------------------------------------------------------------------------
#define G2_SMEM 69632

extern "C" void kernel_launch(void* const* d_in, const int* in_sizes, int n_in,
                              void* d_out, int out_size) {
    const float* x   = (const float*)d_in[0];
    const int*   ei  = (const int*)d_in[1];
    const int*   ty  = (const int*)d_in[2];
    const float* w1  = (const float*)d_in[3];
    const float* b1  = (const float*)d_in[4];
    const float* w2  = (const float*)d_in[5];
    const float* b2  = (const float*)d_in[6];
    const float* lng = (const float*)d_in[7];
    const float* lnb = (const float*)d_in[8];
    const float* mw1 = (const float*)d_in[9];
    const float* mb1 = (const float*)d_in[10];
    const float* mw2 = (const float*)d_in[11];
    const float* mb2 = (const float*)d_in[12];
    float* out = (float*)d_out;

    static bool attr_done = false;
    if (!attr_done) {
        cudaFuncSetAttribute(k_gemm2, cudaFuncAttributeMaxDynamicSharedMemorySize, G2_SMEM);
        attr_done = true;
    }

    k_init<<<(NN + 255) / 256, 256>>>();
    k_pass1<<<(EE + 255) / 256, 256>>>(ei);
    k_pass2<<<(EE + 255) / 256, 256>>>(ei);
    k_prep<<<(256 * 384 + 255) / 256, 256>>>(w1, w2);

    dim3 g1(2, (NN + 127) / 128);
    k_gemm1<<<g1, 256>>>(x, b1);
    k_gemm2<<<(NN + 127) / 128, 256, G2_SMEM>>>(x, b2, lng, lnb, ty, out);
    k_murray<<<592, 256>>>(ty, mw1, mb1, mw2, mb2, out);
}